// round 2
// baseline (speedup 1.0000x reference)
#include <cuda_runtime.h>
#include <math.h>

#define BATCH 4
#define CDIM 256
#define CQK 32
#define HW 4096
#define LOG2E 1.4426950408889634f

// Static scratch: q/k [2][B*HW*32], v [2][B*HW*256]  (~40MB total)
__device__ float g_q[2][BATCH * HW * CQK];
__device__ float g_k[2][BATCH * HW * CQK];
__device__ float g_v[2][BATCH * HW * CDIM];

// ---------------------------------------------------------------------------
// Projection: out[o][p] = sum_c W[o][c] * x[b][c][p] + bias[o]
// o in [0,320): 0-31 -> q, 32-63 -> k, 64-319 -> v
// Block computes a 64(o) x 64(p) tile, K=256 chunked by 32. 256 threads, 4x4 micro.
// ---------------------------------------------------------------------------
__device__ __forceinline__ const float* w_row(int o, const float* Wq,
                                              const float* Wk, const float* Wv) {
    if (o < 32) return Wq + o * CDIM;
    if (o < 64) return Wk + (o - 32) * CDIM;
    return Wv + (o - 64) * CDIM;
}

__global__ __launch_bounds__(256)
void proj_kernel(const float* __restrict__ x,
                 const float* __restrict__ Wq, const float* __restrict__ bq,
                 const float* __restrict__ Wk, const float* __restrict__ bk,
                 const float* __restrict__ Wv, const float* __restrict__ bv,
                 float* __restrict__ qo, float* __restrict__ ko, float* __restrict__ vo) {
    const int otile = blockIdx.x;      // 0..4
    const int p0 = blockIdx.y * 64;    // pixel tile
    const int b = blockIdx.z;

    __shared__ float ws[64 * 33];      // [o_local][c_local]
    __shared__ float xs[32 * 64];      // [c_local][p_local]

    const int tid = threadIdx.x;
    const int tx = tid & 15;           // col group (pixels)
    const int ty = tid >> 4;           // row group (out channels)

    float acc[4][4];
#pragma unroll
    for (int r = 0; r < 4; r++)
#pragma unroll
        for (int s = 0; s < 4; s++) acc[r][s] = 0.0f;

    for (int k0 = 0; k0 < CDIM; k0 += 32) {
        // load W chunk: 64 rows x 32 cols
#pragma unroll
        for (int i = 0; i < 8; i++) {
            int idx = tid + 256 * i;
            int ol = idx >> 5, cl = idx & 31;
            int og = otile * 64 + ol;
            ws[ol * 33 + cl] = w_row(og, Wq, Wk, Wv)[k0 + cl];
        }
        // load x chunk: 32 c x 64 p
#pragma unroll
        for (int i = 0; i < 8; i++) {
            int idx = tid + 256 * i;
            int cl = idx >> 6, pl = idx & 63;
            xs[cl * 64 + pl] = x[((b * CDIM) + (k0 + cl)) * HW + p0 + pl];
        }
        __syncthreads();
#pragma unroll
        for (int cc = 0; cc < 32; cc++) {
            float wf[4];
#pragma unroll
            for (int r = 0; r < 4; r++) wf[r] = ws[(4 * ty + r) * 33 + cc];
            float4 xf = *reinterpret_cast<const float4*>(&xs[cc * 64 + 4 * tx]);
#pragma unroll
            for (int r = 0; r < 4; r++) {
                acc[r][0] = fmaf(wf[r], xf.x, acc[r][0]);
                acc[r][1] = fmaf(wf[r], xf.y, acc[r][1]);
                acc[r][2] = fmaf(wf[r], xf.z, acc[r][2]);
                acc[r][3] = fmaf(wf[r], xf.w, acc[r][3]);
            }
        }
        __syncthreads();
    }

    // epilogue: bias + routed store
#pragma unroll
    for (int r = 0; r < 4; r++) {
        int og = otile * 64 + 4 * ty + r;
        float bias = (og < 32) ? bq[og] : (og < 64) ? bk[og - 32] : bv[og - 64];
#pragma unroll
        for (int s = 0; s < 4; s++) {
            int p = p0 + 4 * tx + s;
            float val = acc[r][s] + bias;
            if (og < 32) {
                qo[(b * HW + p) * CQK + og] = val;
            } else if (og < 64) {
                ko[(b * HW + p) * CQK + (og - 32)] = val;
            } else {
                vo[(b * HW + p) * CDIM + (og - 64)] = val;
            }
        }
    }
}

// ---------------------------------------------------------------------------
// Flash attention: TQ=64 queries per block, stream keys in TK=64 tiles,
// online softmax, 256-dim V accumulation. 256 threads.
// Thread (ty,tx) 16x16 grid: QK^T micro 4x4; PV acc rows 4ty+r, cols tx*4+64k+s.
// ---------------------------------------------------------------------------
#define SM_QS 0                     // 64*33
#define SM_KS (64 * 33)             // 64*33
#define SM_PS (2 * 64 * 33)         // 64*65
#define SM_VS (2 * 64 * 33 + 64 * 65)  // 64*256
#define SMEM_ATTN_FLOATS (2 * 64 * 33 + 64 * 65 + 64 * 256)

__global__ __launch_bounds__(256, 2)
void attn_kernel(float* __restrict__ out_base) {
    extern __shared__ float sm[];
    float* qs = sm + SM_QS;
    float* ks = sm + SM_KS;
    float* ps = sm + SM_PS;
    float* vs = sm + SM_VS;

    const int qt = blockIdx.x;   // 0..63
    const int b = blockIdx.y;    // 0..3
    const int dir = blockIdx.z;  // 0: x->y, 1: y->x

    const float* q = g_q[dir];
    const float* k = g_k[1 - dir];
    const float* v = g_v[1 - dir];
    float* out = out_base + (size_t)dir * BATCH * CDIM * HW;

    const int tid = threadIdx.x;
    const int tx = tid & 15;
    const int ty = tid >> 4;

    // load q tile [64 x 32] (padded 33)
    for (int idx = tid; idx < 64 * 32; idx += 256) {
        int j = idx >> 5, c = idx & 31;
        qs[j * 33 + c] = q[((b * HW) + (qt * 64 + j)) * CQK + c];
    }

    float m[4], l[4], acc[4][16];
#pragma unroll
    for (int r = 0; r < 4; r++) {
        m[r] = -INFINITY;
        l[r] = 0.0f;
#pragma unroll
        for (int c = 0; c < 16; c++) acc[r][c] = 0.0f;
    }

    for (int kt = 0; kt < 64; kt++) {
        __syncthreads();  // previous iteration done reading ks/vs/ps
        // load K tile [64 x 32]
        for (int idx = tid; idx < 64 * 32; idx += 256) {
            int j = idx >> 5, c = idx & 31;
            ks[j * 33 + c] = k[((b * HW) + (kt * 64 + j)) * CQK + c];
        }
        // load V tile [64 x 256] as float4
        const float4* vg = reinterpret_cast<const float4*>(v) +
                           (size_t)(b * HW + kt * 64) * (CDIM / 4);
        float4* vsm = reinterpret_cast<float4*>(vs);
        for (int idx = tid; idx < 64 * (CDIM / 4); idx += 256) {
            vsm[idx] = vg[idx];
        }
        __syncthreads();

        // S = Q K^T  (4x4 per thread)
        float s[4][4];
#pragma unroll
        for (int r = 0; r < 4; r++)
#pragma unroll
            for (int cc = 0; cc < 4; cc++) s[r][cc] = 0.0f;

#pragma unroll
        for (int c = 0; c < 32; c++) {
            float qf[4], kf[4];
#pragma unroll
            for (int r = 0; r < 4; r++) qf[r] = qs[(4 * ty + r) * 33 + c];
#pragma unroll
            for (int cc = 0; cc < 4; cc++) kf[cc] = ks[(4 * tx + cc) * 33 + c];
#pragma unroll
            for (int r = 0; r < 4; r++)
#pragma unroll
                for (int cc = 0; cc < 4; cc++)
                    s[r][cc] = fmaf(qf[r], kf[cc], s[r][cc]);
        }

        // online softmax per row (rows 4ty+r, owned by 16 tx-lanes)
        float alpha[4];
#pragma unroll
        for (int r = 0; r < 4; r++) {
            float tmax = fmaxf(fmaxf(s[r][0], s[r][1]), fmaxf(s[r][2], s[r][3]));
#pragma unroll
            for (int d = 1; d <= 8; d <<= 1)
                tmax = fmaxf(tmax, __shfl_xor_sync(0xFFFFFFFFu, tmax, d));
            float mnew = fmaxf(m[r], tmax);
            alpha[r] = exp2f((m[r] - mnew) * LOG2E);
            float rsum = 0.0f;
#pragma unroll
            for (int cc = 0; cc < 4; cc++) {
                float p = exp2f((s[r][cc] - mnew) * LOG2E);
                s[r][cc] = p;
                rsum += p;
            }
#pragma unroll
            for (int d = 1; d <= 8; d <<= 1)
                rsum += __shfl_xor_sync(0xFFFFFFFFu, rsum, d);
            l[r] = l[r] * alpha[r] + rsum;
            m[r] = mnew;
        }

        // write P to smem, rescale accumulators
#pragma unroll
        for (int r = 0; r < 4; r++) {
#pragma unroll
            for (int cc = 0; cc < 4; cc++)
                ps[(4 * ty + r) * 65 + 4 * tx + cc] = s[r][cc];
#pragma unroll
            for (int c = 0; c < 16; c++) acc[r][c] *= alpha[r];
        }
        __syncthreads();

        // acc += P @ V   (rows 4ty+r, cols tx*4 + 64*kb + s)
#pragma unroll 4
        for (int j = 0; j < 64; j++) {
            float pv[4];
#pragma unroll
            for (int r = 0; r < 4; r++) pv[r] = ps[(4 * ty + r) * 65 + j];
#pragma unroll
            for (int kb = 0; kb < 4; kb++) {
                float4 vv = *reinterpret_cast<const float4*>(
                    &vs[j * CDIM + tx * 4 + 64 * kb]);
#pragma unroll
                for (int r = 0; r < 4; r++) {
                    acc[r][kb * 4 + 0] = fmaf(pv[r], vv.x, acc[r][kb * 4 + 0]);
                    acc[r][kb * 4 + 1] = fmaf(pv[r], vv.y, acc[r][kb * 4 + 1]);
                    acc[r][kb * 4 + 2] = fmaf(pv[r], vv.z, acc[r][kb * 4 + 2]);
                    acc[r][kb * 4 + 3] = fmaf(pv[r], vv.w, acc[r][kb * 4 + 3]);
                }
            }
        }
    }

    // epilogue: normalize and store out[b][c][i]
#pragma unroll
    for (int r = 0; r < 4; r++) {
        float invl = 1.0f / l[r];
        int i = qt * 64 + 4 * ty + r;
#pragma unroll
        for (int kb = 0; kb < 4; kb++) {
#pragma unroll
            for (int s = 0; s < 4; s++) {
                int c = tx * 4 + 64 * kb + s;
                out[((size_t)b * CDIM + c) * HW + i] = acc[r][kb * 4 + s] * invl;
            }
        }
    }
}

// ---------------------------------------------------------------------------
extern "C" void kernel_launch(void* const* d_in, const int* in_sizes, int n_in,
                              void* d_out, int out_size) {
    const float* x  = (const float*)d_in[0];
    const float* y  = (const float*)d_in[1];
    const float* Wq = (const float*)d_in[2];
    const float* bq = (const float*)d_in[3];
    const float* Wk = (const float*)d_in[4];
    const float* bk = (const float*)d_in[5];
    const float* Wv = (const float*)d_in[6];
    const float* bv = (const float*)d_in[7];
    float* out = (float*)d_out;

    float *q0, *k0, *v0, *q1, *k1, *v1;
    cudaGetSymbolAddress((void**)&q0, g_q);
    cudaGetSymbolAddress((void**)&k0, g_k);
    cudaGetSymbolAddress((void**)&v0, g_v);
    q1 = q0 + BATCH * HW * CQK;
    k1 = k0 + BATCH * HW * CQK;
    v1 = v0 + (size_t)BATCH * HW * CDIM;

    static bool attr_set = false;
    if (!attr_set) {
        cudaFuncSetAttribute(attn_kernel, cudaFuncAttributeMaxDynamicSharedMemorySize,
                             SMEM_ATTN_FLOATS * sizeof(float));
        attr_set = true;
    }

    dim3 pgrid(5, HW / 64, BATCH);
    proj_kernel<<<pgrid, 256>>>(x, Wq, bq, Wk, bk, Wv, bv, q0, k0, v0);
    proj_kernel<<<pgrid, 256>>>(y, Wq, bq, Wk, bk, Wv, bv, q1, k1, v1);

    dim3 agrid(HW / 64, BATCH, 2);
    attn_kernel<<<agrid, 256, SMEM_ATTN_FLOATS * sizeof(float)>>>(out);
}

// round 5
// speedup vs baseline: 2.3504x; 2.3504x over previous
#include <cuda_runtime.h>
#include <cuda_bf16.h>
#include <cstdint>
#include <math.h>

#define BATCH 4
#define CDIM 256
#define HW 4096
#define NKT 32
#define NQT 32

typedef unsigned short u16;
typedef uint32_t u32;

// bf16 hi/lo scratch written by proj, read by attn.
// q/k: [dir*4+b][token][32ch]; v: [dir*4+b][ch][4096 tokens]
__device__ u16 g_qh[2 * BATCH * HW * 32];
__device__ u16 g_ql[2 * BATCH * HW * 32];
__device__ u16 g_kh[2 * BATCH * HW * 32];
__device__ u16 g_kl[2 * BATCH * HW * 32];
__device__ u16 g_vh[2 * BATCH * CDIM * HW];
__device__ u16 g_vl[2 * BATCH * CDIM * HW];

// ---------------------------------------------------------------------------
__device__ __forceinline__ void cpa16(u32 dst, const void* src) {
    asm volatile("cp.async.cg.shared.global [%0], [%1], 16;" :: "r"(dst), "l"(src));
}
__device__ __forceinline__ void cp_commit() {
    asm volatile("cp.async.commit_group;" ::: "memory");
}
template <int N> __device__ __forceinline__ void cp_wait() {
    asm volatile("cp.async.wait_group %0;" :: "n"(N) : "memory");
}
__device__ __forceinline__ u32 cvta_smem(const void* p) {
    u32 a;
    asm("{ .reg .u64 t; cvta.to.shared.u64 t, %1; cvt.u32.u64 %0, t; }" : "=r"(a) : "l"(p));
    return a;
}
__device__ __forceinline__ void mma_bf16(float* d, const u32* a, const u32* b) {
    asm volatile(
        "mma.sync.aligned.m16n8k16.row.col.f32.bf16.bf16.f32 "
        "{%0,%1,%2,%3}, {%4,%5,%6,%7}, {%8,%9}, {%0,%1,%2,%3};"
        : "+f"(d[0]), "+f"(d[1]), "+f"(d[2]), "+f"(d[3])
        : "r"(a[0]), "r"(a[1]), "r"(a[2]), "r"(a[3]), "r"(b[0]), "r"(b[1]));
}
__device__ __forceinline__ void split2(float x, float y, u32& hi, u32& lo) {
    __nv_bfloat162 h = __floats2bfloat162_rn(x, y);
    float2 hf = __bfloat1622float2(h);
    __nv_bfloat162 l = __floats2bfloat162_rn(x - hf.x, y - hf.y);
    hi = *reinterpret_cast<u32*>(&h);
    lo = *reinterpret_cast<u32*>(&l);
}

// ---------------------------------------------------------------------------
// Projection GEMM (fp32 FFMA, 102us baseline) with bf16 hi/lo epilogue.
// o 0-31 -> q, 32-63 -> k, 64-319 -> v
// ---------------------------------------------------------------------------
__device__ __forceinline__ const float* w_row(int o, const float* Wq,
                                              const float* Wk, const float* Wv) {
    if (o < 32) return Wq + o * CDIM;
    if (o < 64) return Wk + (o - 32) * CDIM;
    return Wv + (o - 64) * CDIM;
}

__global__ __launch_bounds__(256)
void proj_kernel(const float* __restrict__ x,
                 const float* __restrict__ Wq, const float* __restrict__ bq,
                 const float* __restrict__ Wk, const float* __restrict__ bk,
                 const float* __restrict__ Wv, const float* __restrict__ bv,
                 int dir) {
    const int otile = blockIdx.x;
    const int p0 = blockIdx.y * 64;
    const int b = blockIdx.z;

    __shared__ float ws[64 * 33];
    __shared__ float xs[32 * 64];

    const int tid = threadIdx.x;
    const int tx = tid & 15;
    const int ty = tid >> 4;

    float acc[4][4];
#pragma unroll
    for (int r = 0; r < 4; r++)
#pragma unroll
        for (int s = 0; s < 4; s++) acc[r][s] = 0.0f;

    for (int k0 = 0; k0 < CDIM; k0 += 32) {
#pragma unroll
        for (int i = 0; i < 8; i++) {
            int idx = tid + 256 * i;
            int ol = idx >> 5, cl = idx & 31;
            ws[ol * 33 + cl] = w_row(otile * 64 + ol, Wq, Wk, Wv)[k0 + cl];
        }
#pragma unroll
        for (int i = 0; i < 8; i++) {
            int idx = tid + 256 * i;
            int cl = idx >> 6, pl = idx & 63;
            xs[cl * 64 + pl] = x[((b * CDIM) + (k0 + cl)) * HW + p0 + pl];
        }
        __syncthreads();
#pragma unroll
        for (int cc = 0; cc < 32; cc++) {
            float wf[4];
#pragma unroll
            for (int r = 0; r < 4; r++) wf[r] = ws[(4 * ty + r) * 33 + cc];
            float4 xf = *reinterpret_cast<const float4*>(&xs[cc * 64 + 4 * tx]);
#pragma unroll
            for (int r = 0; r < 4; r++) {
                acc[r][0] = fmaf(wf[r], xf.x, acc[r][0]);
                acc[r][1] = fmaf(wf[r], xf.y, acc[r][1]);
                acc[r][2] = fmaf(wf[r], xf.z, acc[r][2]);
                acc[r][3] = fmaf(wf[r], xf.w, acc[r][3]);
            }
        }
        __syncthreads();
    }

    if (otile == 0) {
        // q (ty<8) / k (ty>=8): 4 consecutive channels per thread, per pixel.
        const bool isq = (ty < 8);
        const int c0 = isq ? 4 * ty : 4 * (ty - 8);
        float bias[4];
#pragma unroll
        for (int r = 0; r < 4; r++)
            bias[r] = isq ? bq[c0 + r] : bk[c0 + r];
        u16* bh = isq ? g_qh : g_kh;
        u16* bl = isq ? g_ql : g_kl;
        const size_t base = (size_t)(dir * BATCH + b) * HW * 32;
#pragma unroll
        for (int s = 0; s < 4; s++) {
            int p = p0 + 4 * tx + s;
            u32 h0, l0, h1, l1;
            split2(acc[0][s] + bias[0], acc[1][s] + bias[1], h0, l0);
            split2(acc[2][s] + bias[2], acc[3][s] + bias[3], h1, l1);
            size_t off = base + (size_t)p * 32 + c0;
            *reinterpret_cast<uint2*>(bh + off) = make_uint2(h0, h1);
            *reinterpret_cast<uint2*>(bl + off) = make_uint2(l0, l1);
        }
    } else {
        // v: channel-major rows, 4 consecutive tokens per thread.
        const int p = p0 + 4 * tx;
        const size_t vbase = (size_t)(dir * BATCH + b) * CDIM * HW;
#pragma unroll
        for (int r = 0; r < 4; r++) {
            int c = (otile - 1) * 64 + 4 * ty + r;
            float bias = bv[c];
            u32 h0, l0, h1, l1;
            split2(acc[r][0] + bias, acc[r][1] + bias, h0, l0);
            split2(acc[r][2] + bias, acc[r][3] + bias, h1, l1);
            size_t off = vbase + (size_t)c * HW + p;
            *reinterpret_cast<uint2*>(g_vh + off) = make_uint2(h0, h1);
            *reinterpret_cast<uint2*>(g_vl + off) = make_uint2(l0, l1);
        }
    }
}

// ---------------------------------------------------------------------------
// HMMA attention. CTA = 128 q-rows x 128-ch half. 8 warps (4m x 2n).
// SMEM byte map:
//   K hi [2 buf][128*80]   @ 0       (20480)
//   K lo [2 buf][128*80]   @ 20480
//   V hi [128ch][272B]     @ 40960   (34816)
//   V lo                   @ 75776
//   P hi [128row][272B]    @ 110592
//   P lo                   @ 145408
//   lsum float[2][128]     @ 180224
// ---------------------------------------------------------------------------
#define SKH 0
#define SKL 20480
#define SVH 40960
#define SVL 75776
#define SPH 110592
#define SPL 145408
#define SLS 180224
#define SMTOT 181248

__global__ __launch_bounds__(256, 1)
void attn_kernel(float* __restrict__ out) {
    extern __shared__ __align__(16) unsigned char sm[];
    const u32 su = cvta_smem(sm);

    const int tid = threadIdx.x;
    const int wid = tid >> 5;
    const int lane = tid & 31;
    const int wm = wid & 3;        // row group (32 rows)
    const int wn = wid >> 2;       // key group (QK) / ch group (PV)
    const int g = lane >> 2;
    const int t = lane & 3;

    const int qt = blockIdx.x;
    const int b = blockIdx.y & 3;
    const int chh = blockIdx.y >> 2;
    const int dir = blockIdx.z;
    const int cd = 1 - dir;

    const u16* kh_g = g_kh + (size_t)(cd * BATCH + b) * HW * 32;
    const u16* kl_g = g_kl + (size_t)(cd * BATCH + b) * HW * 32;
    const u16* vh_g = g_vh + (size_t)((cd * BATCH + b) * CDIM + chh * 128) * HW;
    const u16* vl_g = g_vl + (size_t)((cd * BATCH + b) * CDIM + chh * 128) * HW;

    // ---- async tile loaders -------------------------------------------------
    auto loadK = [&](int kt) {
        int buf = kt & 1;
#pragma unroll
        for (int i = 0; i < 2; i++) {
            int idx = tid + 256 * i;
            int row = idx >> 2, c16 = idx & 3;
            u32 d = su + buf * 10240 + row * 80 + c16 * 16;
            const size_t src = (size_t)(kt * 128 + row) * 32 + c16 * 8;
            cpa16(d + SKH, kh_g + src);
            cpa16(d + SKL, kl_g + src);
        }
    };
    auto loadV = [&](int kt) {
#pragma unroll
        for (int i = 0; i < 8; i++) {
            int idx = tid + 256 * i;
            int row = idx >> 4, c16 = idx & 15;
            u32 d = su + row * 272 + c16 * 16;
            const size_t src = (size_t)row * HW + kt * 128 + c16 * 8;
            cpa16(d + SVH, vh_g + src);
            cpa16(d + SVL, vl_g + src);
        }
    };

    loadK(0); cp_commit();
    loadV(0); cp_commit();

    // ---- persistent Q fragments --------------------------------------------
    u32 qh[2][2][4], ql[2][2][4];
    {
        const u16* qh_g = g_qh + (size_t)(dir * BATCH + b) * HW * 32;
        const u16* ql_g = g_ql + (size_t)(dir * BATCH + b) * HW * 32;
#pragma unroll
        for (int fm = 0; fm < 2; fm++)
#pragma unroll
            for (int kf = 0; kf < 2; kf++) {
                size_t r0 = (size_t)(qt * 128 + wm * 32 + fm * 16 + g) * 32;
                int c = kf * 16 + t * 2;
                qh[fm][kf][0] = *reinterpret_cast<const u32*>(qh_g + r0 + c);
                qh[fm][kf][1] = *reinterpret_cast<const u32*>(qh_g + r0 + 8 * 32 + c);
                qh[fm][kf][2] = *reinterpret_cast<const u32*>(qh_g + r0 + c + 8);
                qh[fm][kf][3] = *reinterpret_cast<const u32*>(qh_g + r0 + 8 * 32 + c + 8);
                ql[fm][kf][0] = *reinterpret_cast<const u32*>(ql_g + r0 + c);
                ql[fm][kf][1] = *reinterpret_cast<const u32*>(ql_g + r0 + 8 * 32 + c);
                ql[fm][kf][2] = *reinterpret_cast<const u32*>(ql_g + r0 + c + 8);
                ql[fm][kf][3] = *reinterpret_cast<const u32*>(ql_g + r0 + 8 * 32 + c + 8);
            }
    }

    float O[2][8][4];
    float ls[4];
#pragma unroll
    for (int fm = 0; fm < 2; fm++)
#pragma unroll
        for (int nf = 0; nf < 8; nf++)
#pragma unroll
            for (int j = 0; j < 4; j++) O[fm][nf][j] = 0.0f;
#pragma unroll
    for (int i = 0; i < 4; i++) ls[i] = 0.0f;

    // ---- main loop over key tiles ------------------------------------------
    for (int kt = 0; kt < NKT; kt++) {
        const int buf = kt & 1;
        if (kt + 1 < NKT) { loadK(kt + 1); cp_commit(); cp_wait<2>(); }
        else              { cp_wait<1>(); }
        __syncthreads();   // K(kt) visible

        // S = Qhi Khi^T + Qlo Khi^T + Qhi Klo^T
        float S[2][8][4];
#pragma unroll
        for (int fm = 0; fm < 2; fm++)
#pragma unroll
            for (int nf = 0; nf < 8; nf++)
#pragma unroll
                for (int j = 0; j < 4; j++) S[fm][nf][j] = 0.0f;

#pragma unroll
        for (int kf = 0; kf < 2; kf++) {
#pragma unroll
            for (int nf = 0; nf < 8; nf++) {
                int key = wn * 64 + nf * 8 + g;
                const unsigned char* ka = sm + buf * 10240 + key * 80 + (kf * 16 + t * 2) * 2;
                u32 bh[2], bl[2];
                bh[0] = *reinterpret_cast<const u32*>(ka + SKH);
                bh[1] = *reinterpret_cast<const u32*>(ka + SKH + 16);
                bl[0] = *reinterpret_cast<const u32*>(ka + SKL);
                bl[1] = *reinterpret_cast<const u32*>(ka + SKL + 16);
#pragma unroll
                for (int fm = 0; fm < 2; fm++) {
                    mma_bf16(S[fm][nf], qh[fm][kf], bh);
                    mma_bf16(S[fm][nf], ql[fm][kf], bh);
                    mma_bf16(S[fm][nf], qh[fm][kf], bl);
                }
            }
        }

        // exp (no max needed: |s| <= ~24), row sums, P -> smem bf16 hi/lo
#pragma unroll
        for (int fm = 0; fm < 2; fm++) {
            int row = wm * 32 + fm * 16 + g;
#pragma unroll
            for (int nf = 0; nf < 8; nf++) {
                float p0 = __expf(S[fm][nf][0]);
                float p1 = __expf(S[fm][nf][1]);
                float p2 = __expf(S[fm][nf][2]);
                float p3 = __expf(S[fm][nf][3]);
                ls[fm * 2 + 0] += p0 + p1;
                ls[fm * 2 + 1] += p2 + p3;
                u32 h01, l01, h23, l23;
                split2(p0, p1, h01, l01);
                split2(p2, p3, h23, l23);
                int ko = (wn * 64 + nf * 8 + t * 2) * 2;
                *reinterpret_cast<u32*>(sm + SPH + row * 272 + ko) = h01;
                *reinterpret_cast<u32*>(sm + SPL + row * 272 + ko) = l01;
                *reinterpret_cast<u32*>(sm + SPH + (row + 8) * 272 + ko) = h23;
                *reinterpret_cast<u32*>(sm + SPL + (row + 8) * 272 + ko) = l23;
            }
        }

        if (kt + 1 < NKT) cp_wait<1>(); else cp_wait<0>();
        __syncthreads();   // V(kt) + P visible

        // O += Phi Vhi + Plo Vhi + Phi Vlo
#pragma unroll
        for (int kf = 0; kf < 8; kf++) {
            u32 ah[2][4], al[2][4];
#pragma unroll
            for (int fm = 0; fm < 2; fm++) {
                int row = wm * 32 + fm * 16 + g;
                int ko = (kf * 16 + t * 2) * 2;
                ah[fm][0] = *reinterpret_cast<const u32*>(sm + SPH + row * 272 + ko);
                ah[fm][1] = *reinterpret_cast<const u32*>(sm + SPH + (row + 8) * 272 + ko);
                ah[fm][2] = *reinterpret_cast<const u32*>(sm + SPH + row * 272 + ko + 16);
                ah[fm][3] = *reinterpret_cast<const u32*>(sm + SPH + (row + 8) * 272 + ko + 16);
                al[fm][0] = *reinterpret_cast<const u32*>(sm + SPL + row * 272 + ko);
                al[fm][1] = *reinterpret_cast<const u32*>(sm + SPL + (row + 8) * 272 + ko);
                al[fm][2] = *reinterpret_cast<const u32*>(sm + SPL + row * 272 + ko + 16);
                al[fm][3] = *reinterpret_cast<const u32*>(sm + SPL + (row + 8) * 272 + ko + 16);
            }
#pragma unroll
            for (int nf = 0; nf < 8; nf++) {
                int ch = wn * 64 + nf * 8 + g;
                int base = ch * 272 + (kf * 16 + t * 2) * 2;
                u32 bh[2], bl[2];
                bh[0] = *reinterpret_cast<const u32*>(sm + SVH + base);
                bh[1] = *reinterpret_cast<const u32*>(sm + SVH + base + 16);
                bl[0] = *reinterpret_cast<const u32*>(sm + SVL + base);
                bl[1] = *reinterpret_cast<const u32*>(sm + SVL + base + 16);
#pragma unroll
                for (int fm = 0; fm < 2; fm++) {
                    mma_bf16(O[fm][nf], ah[fm], bh);
                    mma_bf16(O[fm][nf], al[fm], bh);
                    mma_bf16(O[fm][nf], ah[fm], bl);
                }
            }
        }
        __syncthreads();   // V buffer + P free
        if (kt + 1 < NKT) { loadV(kt + 1); cp_commit(); }
    }

    // ---- epilogue: combine row sums, normalize, store ----------------------
#pragma unroll
    for (int i = 0; i < 4; i++) {
        ls[i] += __shfl_xor_sync(0xffffffffu, ls[i], 1);
        ls[i] += __shfl_xor_sync(0xffffffffu, ls[i], 2);
    }
    float* lsm = reinterpret_cast<float*>(sm + SLS);
    if (t == 0) {
#pragma unroll
        for (int fm = 0; fm < 2; fm++)
#pragma unroll
            for (int h = 0; h < 2; h++)
                lsm[wn * 128 + wm * 32 + fm * 16 + h * 8 + g] = ls[fm * 2 + h];
    }
    __syncthreads();

    float* outp = out + ((size_t)((dir * BATCH + b) * CDIM) + chh * 128) * HW;
#pragma unroll
    for (int fm = 0; fm < 2; fm++) {
        int row0 = wm * 32 + fm * 16 + g;
        float inv0 = 1.0f / (lsm[row0] + lsm[128 + row0]);
        float inv1 = 1.0f / (lsm[row0 + 8] + lsm[128 + row0 + 8]);
        int tok0 = qt * 128 + row0;
#pragma unroll
        for (int nf = 0; nf < 8; nf++) {
            int ch = wn * 64 + nf * 8 + t * 2;
            outp[(size_t)ch * HW + tok0] = O[fm][nf][0] * inv0;
            outp[(size_t)(ch + 1) * HW + tok0] = O[fm][nf][1] * inv0;
            outp[(size_t)ch * HW + tok0 + 8] = O[fm][nf][2] * inv1;
            outp[(size_t)(ch + 1) * HW + tok0 + 8] = O[fm][nf][3] * inv1;
        }
    }
}

// ---------------------------------------------------------------------------
extern "C" void kernel_launch(void* const* d_in, const int* in_sizes, int n_in,
                              void* d_out, int out_size) {
    const float* x  = (const float*)d_in[0];
    const float* y  = (const float*)d_in[1];
    const float* Wq = (const float*)d_in[2];
    const float* bq = (const float*)d_in[3];
    const float* Wk = (const float*)d_in[4];
    const float* bk = (const float*)d_in[5];
    const float* Wv = (const float*)d_in[6];
    const float* bv = (const float*)d_in[7];
    float* out = (float*)d_out;

    static bool attr_set = false;
    if (!attr_set) {
        cudaFuncSetAttribute(attn_kernel, cudaFuncAttributeMaxDynamicSharedMemorySize, SMTOT);
        attr_set = true;
    }

    dim3 pgrid(5, HW / 64, BATCH);
    proj_kernel<<<pgrid, 256>>>(x, Wq, bq, Wk, bk, Wv, bv, 0);
    proj_kernel<<<pgrid, 256>>>(y, Wq, bq, Wk, bk, Wv, bv, 1);

    dim3 agrid(NQT, 2 * BATCH, 2);
    attn_kernel<<<agrid, 256, SMTOT>>>(out);
}

// round 6
// speedup vs baseline: 3.2436x; 1.3800x over previous
#include <cuda_runtime.h>
#include <cuda_bf16.h>
#include <cuda_fp16.h>
#include <cstdint>
#include <math.h>

#define BATCH 4
#define CDIM 256
#define HW 4096
#define NKT 32
#define NQT 32

typedef unsigned short u16;
typedef uint32_t u32;

// q/k: bf16 hi/lo [dir*4+b][token][32ch]; v: fp16 [dir*4+b][ch][4096 tokens]
__device__ u16 g_qh[2 * BATCH * HW * 32];
__device__ u16 g_ql[2 * BATCH * HW * 32];
__device__ u16 g_kh[2 * BATCH * HW * 32];
__device__ u16 g_kl[2 * BATCH * HW * 32];
__device__ u16 g_vh[2 * BATCH * CDIM * HW];

// ---------------------------------------------------------------------------
__device__ __forceinline__ void cpa16(u32 dst, const void* src) {
    asm volatile("cp.async.cg.shared.global [%0], [%1], 16;" :: "r"(dst), "l"(src));
}
__device__ __forceinline__ void cp_commit() {
    asm volatile("cp.async.commit_group;" ::: "memory");
}
template <int N> __device__ __forceinline__ void cp_wait() {
    asm volatile("cp.async.wait_group %0;" :: "n"(N) : "memory");
}
__device__ __forceinline__ u32 cvta_smem(const void* p) {
    u32 a;
    asm("{ .reg .u64 t; cvta.to.shared.u64 t, %1; cvt.u32.u64 %0, t; }" : "=r"(a) : "l"(p));
    return a;
}
__device__ __forceinline__ void mma_bf16(float* d, const u32* a, const u32* b) {
    asm volatile(
        "mma.sync.aligned.m16n8k16.row.col.f32.bf16.bf16.f32 "
        "{%0,%1,%2,%3}, {%4,%5,%6,%7}, {%8,%9}, {%0,%1,%2,%3};"
        : "+f"(d[0]), "+f"(d[1]), "+f"(d[2]), "+f"(d[3])
        : "r"(a[0]), "r"(a[1]), "r"(a[2]), "r"(a[3]), "r"(b[0]), "r"(b[1]));
}
__device__ __forceinline__ void mma_f16h(float* d, const u32* a, const u32* b) {
    asm volatile(
        "mma.sync.aligned.m16n8k16.row.col.f32.f16.f16.f32 "
        "{%0,%1,%2,%3}, {%4,%5,%6,%7}, {%8,%9}, {%0,%1,%2,%3};"
        : "+f"(d[0]), "+f"(d[1]), "+f"(d[2]), "+f"(d[3])
        : "r"(a[0]), "r"(a[1]), "r"(a[2]), "r"(a[3]), "r"(b[0]), "r"(b[1]));
}
__device__ __forceinline__ void split2(float x, float y, u32& hi, u32& lo) {
    __nv_bfloat162 h = __floats2bfloat162_rn(x, y);
    float2 hf = __bfloat1622float2(h);
    __nv_bfloat162 l = __floats2bfloat162_rn(x - hf.x, y - hf.y);
    hi = *reinterpret_cast<u32*>(&h);
    lo = *reinterpret_cast<u32*>(&l);
}

// ---------------------------------------------------------------------------
// Projection GEMM, both dirs in one launch. CTA = 64 out-ch x 128 pixels.
// o 0-31 -> q, 32-63 -> k, 64-319 -> v
// ---------------------------------------------------------------------------
__device__ __forceinline__ const float* w_row(int o, const float* Wq,
                                              const float* Wk, const float* Wv) {
    if (o < 32) return Wq + o * CDIM;
    if (o < 64) return Wk + (o - 32) * CDIM;
    return Wv + (o - 64) * CDIM;
}

__global__ __launch_bounds__(256)
void proj_kernel(const float* __restrict__ x0, const float* __restrict__ y0,
                 const float* __restrict__ Wq, const float* __restrict__ bq,
                 const float* __restrict__ Wk, const float* __restrict__ bk,
                 const float* __restrict__ Wv, const float* __restrict__ bv) {
    const int otile = blockIdx.x;         // 0..4
    const int p0 = blockIdx.y * 128;      // pixel tile
    const int b = blockIdx.z & 3;
    const int dir = blockIdx.z >> 2;
    const float* x = dir ? y0 : x0;

    __shared__ float ws[64 * 33];
    __shared__ float xs[32 * 128];

    const int tid = threadIdx.x;
    const int tx = tid & 15;              // 8 pixels each
    const int ty = tid >> 4;              // 4 out-ch each

    float acc[4][8];
#pragma unroll
    for (int r = 0; r < 4; r++)
#pragma unroll
        for (int s = 0; s < 8; s++) acc[r][s] = 0.0f;

    for (int k0 = 0; k0 < CDIM; k0 += 32) {
#pragma unroll
        for (int i = 0; i < 8; i++) {
            int idx = tid + 256 * i;
            int ol = idx >> 5, cl = idx & 31;
            ws[ol * 33 + cl] = w_row(otile * 64 + ol, Wq, Wk, Wv)[k0 + cl];
        }
#pragma unroll
        for (int i = 0; i < 4; i++) {
            int idx = tid + 256 * i;
            int cl = idx >> 5, p4 = idx & 31;
            *reinterpret_cast<float4*>(&xs[cl * 128 + p4 * 4]) =
                *reinterpret_cast<const float4*>(
                    &x[((size_t)(b * CDIM) + (k0 + cl)) * HW + p0 + p4 * 4]);
        }
        __syncthreads();
#pragma unroll
        for (int cc = 0; cc < 32; cc++) {
            float wf[4];
#pragma unroll
            for (int r = 0; r < 4; r++) wf[r] = ws[(4 * ty + r) * 33 + cc];
            float4 xf0 = *reinterpret_cast<const float4*>(&xs[cc * 128 + 8 * tx]);
            float4 xf1 = *reinterpret_cast<const float4*>(&xs[cc * 128 + 8 * tx + 4]);
#pragma unroll
            for (int r = 0; r < 4; r++) {
                acc[r][0] = fmaf(wf[r], xf0.x, acc[r][0]);
                acc[r][1] = fmaf(wf[r], xf0.y, acc[r][1]);
                acc[r][2] = fmaf(wf[r], xf0.z, acc[r][2]);
                acc[r][3] = fmaf(wf[r], xf0.w, acc[r][3]);
                acc[r][4] = fmaf(wf[r], xf1.x, acc[r][4]);
                acc[r][5] = fmaf(wf[r], xf1.y, acc[r][5]);
                acc[r][6] = fmaf(wf[r], xf1.z, acc[r][6]);
                acc[r][7] = fmaf(wf[r], xf1.w, acc[r][7]);
            }
        }
        __syncthreads();
    }

    if (otile == 0) {
        // q (ty<8) / k (ty>=8): 4 consecutive channels, bf16 hi/lo split
        const bool isq = (ty < 8);
        const int c0 = isq ? 4 * ty : 4 * (ty - 8);
        float bias[4];
#pragma unroll
        for (int r = 0; r < 4; r++)
            bias[r] = isq ? bq[c0 + r] : bk[c0 + r];
        u16* bh = isq ? g_qh : g_kh;
        u16* bl = isq ? g_ql : g_kl;
        const size_t base = (size_t)(dir * BATCH + b) * HW * 32;
#pragma unroll
        for (int s = 0; s < 8; s++) {
            int p = p0 + 8 * tx + s;
            u32 h0, l0, h1, l1;
            split2(acc[0][s] + bias[0], acc[1][s] + bias[1], h0, l0);
            split2(acc[2][s] + bias[2], acc[3][s] + bias[3], h1, l1);
            size_t off = base + (size_t)p * 32 + c0;
            *reinterpret_cast<uint2*>(bh + off) = make_uint2(h0, h1);
            *reinterpret_cast<uint2*>(bl + off) = make_uint2(l0, l1);
        }
    } else {
        // v: fp16, channel-major, 8 consecutive tokens per thread
        const int p = p0 + 8 * tx;
        const size_t vbase = (size_t)(dir * BATCH + b) * CDIM * HW;
#pragma unroll
        for (int r = 0; r < 4; r++) {
            int c = (otile - 1) * 64 + 4 * ty + r;
            float bias = bv[c];
            __half2 a0 = __floats2half2_rn(acc[r][0] + bias, acc[r][1] + bias);
            __half2 a1 = __floats2half2_rn(acc[r][2] + bias, acc[r][3] + bias);
            __half2 a2 = __floats2half2_rn(acc[r][4] + bias, acc[r][5] + bias);
            __half2 a3 = __floats2half2_rn(acc[r][6] + bias, acc[r][7] + bias);
            uint4 val;
            val.x = *reinterpret_cast<u32*>(&a0);
            val.y = *reinterpret_cast<u32*>(&a1);
            val.z = *reinterpret_cast<u32*>(&a2);
            val.w = *reinterpret_cast<u32*>(&a3);
            *reinterpret_cast<uint4*>(g_vh + vbase + (size_t)c * HW + p) = val;
        }
    }
}

// ---------------------------------------------------------------------------
// HMMA attention with flash m/l. CTA = 128 q-rows x 128-ch half, 8 warps.
// QK: bf16 3-product (exact logits). PV: single fp16 product.
// SMEM byte map:
//   K hi [2][128*80] @0 (20480) | K lo @20480 | V fp16 [128][272] @40960
//   P fp16 [128][272] @75776 | lsum[2][128] @110592 | rowmax[2][128] @111616
// ---------------------------------------------------------------------------
#define SKH 0
#define SKL 20480
#define SV  40960
#define SP  75776
#define SLS 110592
#define SMX 111616
#define SMTOT 112640

__global__ __launch_bounds__(256, 1)
void attn_kernel(float* __restrict__ out) {
    extern __shared__ __align__(16) unsigned char sm[];
    const u32 su = cvta_smem(sm);

    const int tid = threadIdx.x;
    const int wid = tid >> 5;
    const int lane = tid & 31;
    const int wm = wid & 3;        // row group (32 rows)
    const int wn = wid >> 2;       // key group (QK) / ch group (PV)
    const int g = lane >> 2;
    const int t = lane & 3;

    const int qt = blockIdx.x;
    const int b = blockIdx.y & 3;
    const int chh = blockIdx.y >> 2;
    const int dir = blockIdx.z;
    const int cd = 1 - dir;

    const u16* kh_g = g_kh + (size_t)(cd * BATCH + b) * HW * 32;
    const u16* kl_g = g_kl + (size_t)(cd * BATCH + b) * HW * 32;
    const u16* vh_g = g_vh + (size_t)((cd * BATCH + b) * CDIM + chh * 128) * HW;

    auto loadK = [&](int kt) {
        int buf = kt & 1;
#pragma unroll
        for (int i = 0; i < 2; i++) {
            int idx = tid + 256 * i;
            int row = idx >> 2, c16 = idx & 3;
            u32 d = su + buf * 10240 + row * 80 + c16 * 16;
            const size_t src = (size_t)(kt * 128 + row) * 32 + c16 * 8;
            cpa16(d + SKH, kh_g + src);
            cpa16(d + SKL, kl_g + src);
        }
    };
    auto loadV = [&](int kt) {
#pragma unroll
        for (int i = 0; i < 8; i++) {
            int idx = tid + 256 * i;
            int row = idx >> 4, c16 = idx & 15;
            u32 d = su + SV + row * 272 + c16 * 16;
            cpa16(d, vh_g + (size_t)row * HW + kt * 128 + c16 * 8);
        }
    };

    loadK(0); cp_commit();
    loadV(0); cp_commit();

    // persistent Q fragments (bf16 hi/lo)
    u32 qh[2][2][4], ql[2][2][4];
    {
        const u16* qh_g = g_qh + (size_t)(dir * BATCH + b) * HW * 32;
        const u16* ql_g = g_ql + (size_t)(dir * BATCH + b) * HW * 32;
#pragma unroll
        for (int fm = 0; fm < 2; fm++)
#pragma unroll
            for (int kf = 0; kf < 2; kf++) {
                size_t r0 = (size_t)(qt * 128 + wm * 32 + fm * 16 + g) * 32;
                int c = kf * 16 + t * 2;
                qh[fm][kf][0] = *reinterpret_cast<const u32*>(qh_g + r0 + c);
                qh[fm][kf][1] = *reinterpret_cast<const u32*>(qh_g + r0 + 8 * 32 + c);
                qh[fm][kf][2] = *reinterpret_cast<const u32*>(qh_g + r0 + c + 8);
                qh[fm][kf][3] = *reinterpret_cast<const u32*>(qh_g + r0 + 8 * 32 + c + 8);
                ql[fm][kf][0] = *reinterpret_cast<const u32*>(ql_g + r0 + c);
                ql[fm][kf][1] = *reinterpret_cast<const u32*>(ql_g + r0 + 8 * 32 + c);
                ql[fm][kf][2] = *reinterpret_cast<const u32*>(ql_g + r0 + c + 8);
                ql[fm][kf][3] = *reinterpret_cast<const u32*>(ql_g + r0 + 8 * 32 + c + 8);
            }
    }

    float O[2][8][4];
    float ls[4], m[4];
#pragma unroll
    for (int fm = 0; fm < 2; fm++)
#pragma unroll
        for (int nf = 0; nf < 8; nf++)
#pragma unroll
            for (int j = 0; j < 4; j++) O[fm][nf][j] = 0.0f;
#pragma unroll
    for (int i = 0; i < 4; i++) { ls[i] = 0.0f; m[i] = -1e30f; }

    for (int kt = 0; kt < NKT; kt++) {
        const int buf = kt & 1;
        if (kt + 1 < NKT) { loadK(kt + 1); cp_commit(); cp_wait<2>(); }
        else              { cp_wait<1>(); }
        __syncthreads();   // K(kt) visible

        // S = Qhi Khi^T + Qlo Khi^T + Qhi Klo^T   (bf16, exact to ~2^-16)
        float S[2][8][4];
#pragma unroll
        for (int fm = 0; fm < 2; fm++)
#pragma unroll
            for (int nf = 0; nf < 8; nf++)
#pragma unroll
                for (int j = 0; j < 4; j++) S[fm][nf][j] = 0.0f;

#pragma unroll
        for (int kf = 0; kf < 2; kf++) {
#pragma unroll
            for (int nf = 0; nf < 8; nf++) {
                int key = wn * 64 + nf * 8 + g;
                const unsigned char* ka = sm + buf * 10240 + key * 80 + (kf * 16 + t * 2) * 2;
                u32 bh[2], bl[2];
                bh[0] = *reinterpret_cast<const u32*>(ka + SKH);
                bh[1] = *reinterpret_cast<const u32*>(ka + SKH + 16);
                bl[0] = *reinterpret_cast<const u32*>(ka + SKL);
                bl[1] = *reinterpret_cast<const u32*>(ka + SKL + 16);
#pragma unroll
                for (int fm = 0; fm < 2; fm++) {
                    mma_bf16(S[fm][nf], qh[fm][kf], bh);
                    mma_bf16(S[fm][nf], ql[fm][kf], bh);
                    mma_bf16(S[fm][nf], qh[fm][kf], bl);
                }
            }
        }

        // ---- row max: thread-local -> shfl over t -> smem across wn ----
        float tmax[4];
#pragma unroll
        for (int fm = 0; fm < 2; fm++)
#pragma unroll
            for (int h = 0; h < 2; h++) {
                float v = -1e30f;
#pragma unroll
                for (int nf = 0; nf < 8; nf++)
                    v = fmaxf(v, fmaxf(S[fm][nf][2 * h], S[fm][nf][2 * h + 1]));
                tmax[fm * 2 + h] = v;
            }
#pragma unroll
        for (int i = 0; i < 4; i++) {
            tmax[i] = fmaxf(tmax[i], __shfl_xor_sync(0xffffffffu, tmax[i], 1));
            tmax[i] = fmaxf(tmax[i], __shfl_xor_sync(0xffffffffu, tmax[i], 2));
        }
        float* mx = reinterpret_cast<float*>(sm + SMX);
        if (t == 0) {
#pragma unroll
            for (int fm = 0; fm < 2; fm++)
#pragma unroll
                for (int h = 0; h < 2; h++)
                    mx[wn * 128 + wm * 32 + fm * 16 + h * 8 + g] = tmax[fm * 2 + h];
        }
        __syncthreads();

        float alpha[4];
#pragma unroll
        for (int fm = 0; fm < 2; fm++)
#pragma unroll
            for (int h = 0; h < 2; h++) {
                int i = fm * 2 + h;
                int row = wm * 32 + fm * 16 + h * 8 + g;
                float mn = fmaxf(m[i], fmaxf(mx[row], mx[128 + row]));
                alpha[i] = __expf(m[i] - mn);
                m[i] = mn;
                ls[i] *= alpha[i];
            }

        // exp, P -> smem fp16, rescale O
#pragma unroll
        for (int fm = 0; fm < 2; fm++) {
            int row = wm * 32 + fm * 16 + g;
#pragma unroll
            for (int nf = 0; nf < 8; nf++) {
                float p0 = __expf(S[fm][nf][0] - m[fm * 2]);
                float p1 = __expf(S[fm][nf][1] - m[fm * 2]);
                float p2 = __expf(S[fm][nf][2] - m[fm * 2 + 1]);
                float p3 = __expf(S[fm][nf][3] - m[fm * 2 + 1]);
                ls[fm * 2] += p0 + p1;
                ls[fm * 2 + 1] += p2 + p3;
                __half2 hA = __floats2half2_rn(p0, p1);
                __half2 hB = __floats2half2_rn(p2, p3);
                int ko = (wn * 64 + nf * 8 + t * 2) * 2;
                *reinterpret_cast<u32*>(sm + SP + row * 272 + ko) = *reinterpret_cast<u32*>(&hA);
                *reinterpret_cast<u32*>(sm + SP + (row + 8) * 272 + ko) = *reinterpret_cast<u32*>(&hB);
            }
#pragma unroll
            for (int nf = 0; nf < 8; nf++) {
                O[fm][nf][0] *= alpha[fm * 2];
                O[fm][nf][1] *= alpha[fm * 2];
                O[fm][nf][2] *= alpha[fm * 2 + 1];
                O[fm][nf][3] *= alpha[fm * 2 + 1];
            }
        }

        if (kt + 1 < NKT) cp_wait<1>(); else cp_wait<0>();
        __syncthreads();   // V(kt) + P visible

        // O += P V  (single fp16 product)
#pragma unroll
        for (int kf = 0; kf < 8; kf++) {
            u32 a[2][4];
#pragma unroll
            for (int fm = 0; fm < 2; fm++) {
                int row = wm * 32 + fm * 16 + g;
                int ko = (kf * 16 + t * 2) * 2;
                a[fm][0] = *reinterpret_cast<const u32*>(sm + SP + row * 272 + ko);
                a[fm][1] = *reinterpret_cast<const u32*>(sm + SP + (row + 8) * 272 + ko);
                a[fm][2] = *reinterpret_cast<const u32*>(sm + SP + row * 272 + ko + 16);
                a[fm][3] = *reinterpret_cast<const u32*>(sm + SP + (row + 8) * 272 + ko + 16);
            }
#pragma unroll
            for (int nf = 0; nf < 8; nf++) {
                int ch = wn * 64 + nf * 8 + g;
                int base = ch * 272 + (kf * 16 + t * 2) * 2;
                u32 b2[2];
                b2[0] = *reinterpret_cast<const u32*>(sm + SV + base);
                b2[1] = *reinterpret_cast<const u32*>(sm + SV + base + 16);
#pragma unroll
                for (int fm = 0; fm < 2; fm++)
                    mma_f16h(O[fm][nf], a[fm], b2);
            }
        }
        __syncthreads();   // V buffer + P free
        if (kt + 1 < NKT) { loadV(kt + 1); cp_commit(); }
    }

    // ---- epilogue ----
#pragma unroll
    for (int i = 0; i < 4; i++) {
        ls[i] += __shfl_xor_sync(0xffffffffu, ls[i], 1);
        ls[i] += __shfl_xor_sync(0xffffffffu, ls[i], 2);
    }
    float* lsm = reinterpret_cast<float*>(sm + SLS);
    if (t == 0) {
#pragma unroll
        for (int fm = 0; fm < 2; fm++)
#pragma unroll
            for (int h = 0; h < 2; h++)
                lsm[wn * 128 + wm * 32 + fm * 16 + h * 8 + g] = ls[fm * 2 + h];
    }
    __syncthreads();

    float* outp = out + ((size_t)((dir * BATCH + b) * CDIM) + chh * 128) * HW;
#pragma unroll
    for (int fm = 0; fm < 2; fm++) {
        int row0 = wm * 32 + fm * 16 + g;
        float inv0 = 1.0f / (lsm[row0] + lsm[128 + row0]);
        float inv1 = 1.0f / (lsm[row0 + 8] + lsm[128 + row0 + 8]);
        int tok0 = qt * 128 + row0;
#pragma unroll
        for (int nf = 0; nf < 8; nf++) {
            int ch = wn * 64 + nf * 8 + t * 2;
            outp[(size_t)ch * HW + tok0] = O[fm][nf][0] * inv0;
            outp[(size_t)(ch + 1) * HW + tok0] = O[fm][nf][1] * inv0;
            outp[(size_t)ch * HW + tok0 + 8] = O[fm][nf][2] * inv1;
            outp[(size_t)(ch + 1) * HW + tok0 + 8] = O[fm][nf][3] * inv1;
        }
    }
}

// ---------------------------------------------------------------------------
extern "C" void kernel_launch(void* const* d_in, const int* in_sizes, int n_in,
                              void* d_out, int out_size) {
    const float* x  = (const float*)d_in[0];
    const float* y  = (const float*)d_in[1];
    const float* Wq = (const float*)d_in[2];
    const float* bq = (const float*)d_in[3];
    const float* Wk = (const float*)d_in[4];
    const float* bk = (const float*)d_in[5];
    const float* Wv = (const float*)d_in[6];
    const float* bv = (const float*)d_in[7];
    float* out = (float*)d_out;

    static bool attr_set = false;
    if (!attr_set) {
        cudaFuncSetAttribute(attn_kernel, cudaFuncAttributeMaxDynamicSharedMemorySize, SMTOT);
        attr_set = true;
    }

    dim3 pgrid(5, HW / 128, 2 * BATCH);
    proj_kernel<<<pgrid, 256>>>(x, y, Wq, bq, Wk, bk, Wv, bv);

    dim3 agrid(NQT, 2 * BATCH, 2);
    attn_kernel<<<agrid, 256, SMTOT>>>(out);
}